// round 5
// baseline (speedup 1.0000x reference)
#include <cuda_runtime.h>
#include <cuda_bf16.h>

// Problem constants (fixed by the dataset)
#define NT 4            // B*C trees
#define NN 262144       // nodes per tree (2^18)
#define NPIX (1024*1024)
#define TOTN (NT*NN)            // 1,048,576 nodes total
#define TOTP (NT*NPIX)          // 4,194,304 pixels total

// g_pack[i]: lo32 = float bits of levels[i], hi32 = float bits of v[i].
// v[i] >= levels[root] >= 0.1 > 0 always, so hi32 != 0 serves as the ready flag.
// Zeroed via cudaMemsetAsync at the start of every launch.
__device__ unsigned long long g_pack[TOTN];
__device__ float g_v[TOTN];     // compact values for the pixel gather (fully overwritten)

__device__ __forceinline__ unsigned long long ld_gpu(const unsigned long long* p) {
    unsigned long long v;
    asm volatile("ld.relaxed.gpu.global.u64 %0, [%1];" : "=l"(v) : "l"(p));
    return v;
}
__device__ __forceinline__ void st_gpu(unsigned long long* p, unsigned long long v) {
    asm volatile("st.relaxed.gpu.global.u64 [%0], %1;" :: "l"(p), "l"(v));
}

// ---------------------------------------------------------------------------
// Single-pass chained solve. parent[i] < i strictly, blocks dispatch in
// ascending order, and Volta+ independent thread scheduling guarantees spin
// progress (per-thread publishes happen inside the divergent path, in
// ascending node order, so all waits point to strictly smaller nodes: no cycle).
// ---------------------------------------------------------------------------
__global__ void k_solve(const float* __restrict__ attr,
                        const float* __restrict__ levels,
                        const float* __restrict__ thr,
                        const int*   __restrict__ parent)
{
    int t = blockIdx.x * blockDim.x + threadIdx.x;
    if (t >= TOTN / 4) return;
    int idx = t * 4;
    int base = idx & ~(NN - 1);
    int i0 = idx & (NN - 1);

    float4 lv = __ldg(reinterpret_cast<const float4*>(levels) + t);
    float4 at = __ldg(reinterpret_cast<const float4*>(attr) + t);
    int4   pp = __ldg(reinterpret_cast<const int4*>(parent) + t);
    float  th = __ldg(thr);

    float l[4] = {lv.x, lv.y, lv.z, lv.w};
    float a[4] = {at.x, at.y, at.z, at.w};
    int   p[4] = {pp.x, pp.y, pp.z, pp.w};
    float sg[4], v[4];
#pragma unroll
    for (int k = 0; k < 4; k++) {
        float z = fminf(fmaxf(1000.0f * (a[k] - th), -12.0f), 12.0f);
        sg[k] = 1.0f / (1.0f + __expf(-z));
    }

    // classify parents; fire optimistic loads for all out-of-group parents (MLP 4)
    bool loc[4];
    unsigned long long u[4];
#pragma unroll
    for (int k = 0; k < 4; k++) {
        bool isroot = (i0 + k == 0);
        loc[k] = (p[k] >= i0) && !isroot;     // parent inside this thread's 4-node group
        u[k] = 0ull;
        if (!loc[k] && !isroot) u[k] = ld_gpu(&g_pack[base + p[k]]);
    }

#pragma unroll
    for (int k = 0; k < 4; k++) {
        float vk;
        if (i0 + k == 0) {
            vk = l[k];                         // root: v = c = levels[0]
        } else if (loc[k]) {
            int j = p[k] - i0;                 // 0..k-1, resolved earlier this thread
            float lj = (j == 0) ? l[0] : ((j == 1) ? l[1] : l[2]);
            float vj = (j == 0) ? v[0] : ((j == 1) ? v[1] : v[2]);
            vk = vj + sg[k] * (l[k] - lj);
        } else {
            unsigned long long uu = u[k];
            while ((uu >> 32) == 0ull) {       // not yet published
                __nanosleep(32);
                uu = ld_gpu(&g_pack[base + p[k]]);
            }
            float lp = __int_as_float((int)(unsigned)(uu & 0xffffffffull));
            float vp = __int_as_float((int)(unsigned)(uu >> 32));
            vk = vp + sg[k] * (l[k] - lp);
        }
        v[k] = vk;
        unsigned long long out =
            ((unsigned long long)(unsigned)__float_as_int(vk) << 32)
            | (unsigned)__float_as_int(l[k]);
        st_gpu(&g_pack[idx + k], out);         // publish immediately (in node order)
    }

    reinterpret_cast<float4*>(g_v)[t] = make_float4(v[0], v[1], v[2], v[3]);
}

// ---------------------------------------------------------------------------
// Pixel gather: y[p] = v[tree(p)*NN + pixel_to_node[p]], 4 pixels per thread
// ---------------------------------------------------------------------------
__global__ void k_gather(const int* __restrict__ ptn, float* __restrict__ y)
{
    int q = blockIdx.x * blockDim.x + threadIdx.x;   // quad index
    if (q >= TOTP / 4) return;
    int p0 = q * 4;
    int base = (p0 >> 20) << 18;                     // tree * NN  (NPIX = 2^20)

    int4 n = __ldg(reinterpret_cast<const int4*>(ptn) + q);
    float4 o;
    o.x = __ldg(&g_v[base + n.x]);
    o.y = __ldg(&g_v[base + n.y]);
    o.z = __ldg(&g_v[base + n.z]);
    o.w = __ldg(&g_v[base + n.w]);
    reinterpret_cast<float4*>(y)[q] = o;
}

// ---------------------------------------------------------------------------
extern "C" void kernel_launch(void* const* d_in, const int* in_sizes, int n_in,
                              void* d_out, int out_size)
{
    // metadata order: x, attr_norm, levels, thr, parent, pixel_to_node
    const float* attr   = (const float*)d_in[1];
    const float* levels = (const float*)d_in[2];
    const float* thr    = (const float*)d_in[3];
    const int*   parent = (const int*)d_in[4];
    const int*   ptn    = (const int*)d_in[5];
    float*       y      = (float*)d_out;

    void* pPack = nullptr;
    cudaGetSymbolAddress(&pPack, g_pack);
    cudaMemsetAsync(pPack, 0, TOTN * sizeof(unsigned long long));

    const int TPB = 256;
    k_solve<<<(TOTN / 4) / TPB, TPB>>>(attr, levels, thr, parent);
    k_gather<<<(TOTP / 4) / TPB, TPB>>>(ptn, y);
}

// round 6
// speedup vs baseline: 3.6737x; 3.6737x over previous
#include <cuda_runtime.h>
#include <cuda_bf16.h>

// Problem constants (fixed by the dataset)
#define NT 4            // B*C trees
#define NN 262144       // nodes per tree (2^18)
#define NPIX (1024*1024)
#define TOTN (NT*NN)            // 1,048,576 nodes total
#define TOTP (NT*NPIX)          // 4,194,304 pixels total

// Jump tables (ping-pong). entry = (ptr, s):
//   ptr = ancestor J levels up (0 = chain terminated at root)
//   s   = float bits of sum of c over the covered path segment (excl. root's c0)
// entry[0] = (0, c0) where c0 = levels[0].
__device__ int2 g_bufA[TOTN];
__device__ int2 g_bufB[TOTN];

// ---------------------------------------------------------------------------
// K1 (ILP4): base jump-1 table. c[i] = sigmoid(clamp(1000*(attr-thr),-12,12))
//            * (levels[i]-levels[p]);  entry[0] = (0, levels[0]).
// ---------------------------------------------------------------------------
__global__ void k_build(const float* __restrict__ attr,
                        const float* __restrict__ levels,
                        const float* __restrict__ thr,
                        const int*   __restrict__ parent)
{
    int t = blockIdx.x * blockDim.x + threadIdx.x;
    if (t >= TOTN / 4) return;
    int idx = t * 4;                       // NN % 4 == 0 -> same tree for all 4
    int base = idx & ~(NN - 1);
    int i0 = idx & (NN - 1);

    float4 lv = __ldg(reinterpret_cast<const float4*>(levels) + t);
    float4 at = __ldg(reinterpret_cast<const float4*>(attr) + t);
    int4   pp = __ldg(reinterpret_cast<const int4*>(parent) + t);
    float  th = __ldg(thr);

    float lp0 = __ldg(&levels[base + pp.x]);
    float lp1 = __ldg(&levels[base + pp.y]);
    float lp2 = __ldg(&levels[base + pp.z]);
    float lp3 = __ldg(&levels[base + pp.w]);

    float l[4] = {lv.x, lv.y, lv.z, lv.w};
    float a[4] = {at.x, at.y, at.z, at.w};
    float lp[4] = {lp0, lp1, lp2, lp3};
    int   p[4] = {pp.x, pp.y, pp.z, pp.w};

    int2 out[4];
#pragma unroll
    for (int k = 0; k < 4; k++) {
        float z = fminf(fmaxf(1000.0f * (a[k] - th), -12.0f), 12.0f);
        float s = 1.0f / (1.0f + __expf(-z));
        float c = s * (l[k] - lp[k]);
        int pk = p[k];
        if (i0 + k == 0) { pk = 0; c = l[k]; }     // root entry: (0, c0)
        out[k] = make_int2(pk, __float_as_int(c));
    }
    reinterpret_cast<int4*>(g_bufA)[t * 2 + 0] = make_int4(out[0].x, out[0].y, out[1].x, out[1].y);
    reinterpret_cast<int4*>(g_bufA)[t * 2 + 1] = make_int4(out[2].x, out[2].y, out[3].x, out[3].y);
}

// ---------------------------------------------------------------------------
// K2,K3 (ILP4): triple pass. out_i = e_i ∘ e[ptr_i] ∘ e[ptr[ptr_i]]
// One pass turns jump-J into jump-3J (2 gathers, second dependent).
// ---------------------------------------------------------------------------
__global__ void k_triple(const int2* __restrict__ in, int2* __restrict__ out)
{
    int t = blockIdx.x * blockDim.x + threadIdx.x;
    if (t >= TOTN / 4) return;
    int idx = t * 4;
    int base = idx & ~(NN - 1);

    int4 r0 = __ldg(reinterpret_cast<const int4*>(in) + t * 2 + 0);
    int4 r1 = __ldg(reinterpret_cast<const int4*>(in) + t * 2 + 1);
    int2 e[4] = { make_int2(r0.x, r0.y), make_int2(r0.z, r0.w),
                  make_int2(r1.x, r1.y), make_int2(r1.z, r1.w) };

    // level-1 gathers: 4 independent loads in flight
    int2 b[4];
#pragma unroll
    for (int k = 0; k < 4; k++)
        b[k] = __ldg(&in[base + (e[k].x != 0 ? e[k].x : 0)]);

    // level-2 gathers (dependent): 4 independent loads in flight
    int2 c[4];
#pragma unroll
    for (int k = 0; k < 4; k++) {
        int p2 = (e[k].x != 0 && b[k].x != 0) ? b[k].x : 0;
        c[k] = __ldg(&in[base + p2]);
    }

#pragma unroll
    for (int k = 0; k < 4; k++) {
        if (e[k].x != 0) {
            float s2 = __int_as_float(e[k].y) + __int_as_float(b[k].y);
            if (b[k].x != 0) {
                e[k].x = c[k].x;
                e[k].y = __float_as_int(s2 + __int_as_float(c[k].y));
            } else {
                e[k].x = 0;
                e[k].y = __float_as_int(s2);
            }
        }
    }
    reinterpret_cast<int4*>(out)[t * 2 + 0] = make_int4(e[0].x, e[0].y, e[1].x, e[1].y);
    reinterpret_cast<int4*>(out)[t * 2 + 1] = make_int4(e[2].x, e[2].y, e[3].x, e[3].y);
}

// ---------------------------------------------------------------------------
// K4 (ILP4): fused climb + pixel gather over the jump-9 table.
// y[p] = c0 + sum of segment sums starting at node ptn[p].
// After the first hop, indices shrink ~e^-9 -> second-hop gathers are
// sector-coalesced and L1-hot.
// ---------------------------------------------------------------------------
__global__ void k_pix(const int2* __restrict__ jp,
                      const int*  __restrict__ ptn,
                      float*      __restrict__ y)
{
    int q = blockIdx.x * blockDim.x + threadIdx.x;   // quad index
    if (q >= TOTP / 4) return;
    int p0 = q * 4;
    int tb = (p0 >> 20) << 18;                       // tree * NN  (NPIX = 2^20)

    float c0 = __int_as_float(__ldg(&jp[tb].y));     // root: c0 = levels[0]
    int4 n = __ldg(reinterpret_cast<const int4*>(ptn) + q);

    int   j[4]   = {n.x, n.y, n.z, n.w};
    float acc[4] = {c0, c0, c0, c0};

    while ((j[0] | j[1] | j[2] | j[3]) != 0) {
        int2 a[4];
#pragma unroll
        for (int k = 0; k < 4; k++)
            a[k] = __ldg(&jp[tb + j[k]]);            // 4 loads in flight
#pragma unroll
        for (int k = 0; k < 4; k++) {
            if (j[k] != 0) {
                acc[k] += __int_as_float(a[k].y);
                j[k] = a[k].x;
            }
        }
    }
    reinterpret_cast<float4*>(y)[q] = make_float4(acc[0], acc[1], acc[2], acc[3]);
}

// ---------------------------------------------------------------------------
extern "C" void kernel_launch(void* const* d_in, const int* in_sizes, int n_in,
                              void* d_out, int out_size)
{
    // metadata order: x, attr_norm, levels, thr, parent, pixel_to_node
    const float* attr   = (const float*)d_in[1];
    const float* levels = (const float*)d_in[2];
    const float* thr    = (const float*)d_in[3];
    const int*   parent = (const int*)d_in[4];
    const int*   ptn    = (const int*)d_in[5];
    float*       y      = (float*)d_out;

    void *pA = nullptr, *pB = nullptr;
    cudaGetSymbolAddress(&pA, g_bufA);
    cudaGetSymbolAddress(&pB, g_bufB);
    int2* A = (int2*)pA;
    int2* B = (int2*)pB;

    const int TPB = 256;
    const int gbN4 = (TOTN / 4) / TPB;

    k_build<<<gbN4, TPB>>>(attr, levels, thr, parent);
    k_triple<<<gbN4, TPB>>>(A, B);   // jump-1 -> jump-3
    k_triple<<<gbN4, TPB>>>(B, A);   // jump-3 -> jump-9

    const int gbP = (TOTP / 4) / TPB;
    k_pix<<<gbP, TPB>>>(A, ptn, y);
}